// round 7
// baseline (speedup 1.0000x reference)
#include <cuda_runtime.h>
#include <math.h>

#define TT   1024
#define DD   256
#define HH   256
#define LDP  1024
#define PITCH 72

// ---------------- persistent device scratch ----------------
__device__ float    g_P  [TT*LDP];   // f32: cols [768,1024) = skip
__device__ float    g_Ph [TT*LDP];   // tf32-hi: [0,256)=k [256,512)=q [512,768)=v
__device__ float    g_Pl [TT*LDP];   // tf32-lo
__device__ float    g_Ah [TT*TT],  g_Al [TT*TT];    // masked scores hi/lo
__device__ float    g_Oh [TT*HH],  g_Ol [TT*HH];
__device__ float    g_H1h[TT*HH],  g_H1l[TT*HH];
__device__ float    g_H2h[TT*HH],  g_H2l[TT*HH];
__device__ float    g_H3 [TT*HH];
__device__ unsigned g_M  [TT*32];
__device__ float    g_den[TT], g_ksum[TT], g_qsum[TT];
__device__ unsigned g_Dm[2048*32], g_Sm[2048*32];
__device__ int      g_Dg[2048];

// ---------------- tf32 helpers ----------------
__device__ __forceinline__ float tf32r(float f) {
    unsigned u; asm("cvt.rna.tf32.f32 %0,%1;" : "=r"(u) : "f"(f));
    return __uint_as_float(u);
}
__device__ __forceinline__ float2 splitf(float f) {
    float h = tf32r(f);
    return make_float2(h, tf32r(f - h));
}
__device__ __forceinline__ void mma_tf32(float d[4], const float a[4], const float b[2]) {
    asm volatile(
        "mma.sync.aligned.m16n8k8.row.col.f32.tf32.tf32.f32 "
        "{%0,%1,%2,%3},{%4,%5,%6,%7},{%8,%9},{%0,%1,%2,%3};"
        : "+f"(d[0]), "+f"(d[1]), "+f"(d[2]), "+f"(d[3])
        : "r"(__float_as_uint(a[0])), "r"(__float_as_uint(a[1])),
          "r"(__float_as_uint(a[2])), "r"(__float_as_uint(a[3])),
          "r"(__float_as_uint(b[0])), "r"(__float_as_uint(b[1])));
}

// ---------------- stage compute: 16 k on current smem buffers ----------------
// warp tile: rows wm*32 + mt*16, cols wn*8*NT + nt*8. 3xTF32: hh + hl + lh.
template<int NT>
__device__ __forceinline__ void stage_compute(
    const float (*sAh)[PITCH], const float (*sAl)[PITCH],
    const float (*sBh)[PITCH], const float (*sBl)[PITCH],
    float d[2][NT][4], int wm, int wn, int g, int t4)
{
#pragma unroll
    for (int kb = 0; kb < 16; kb += 8) {
        float ah[2][4], al[2][4], bh[NT][2], bl[NT][2];
#pragma unroll
        for (int mt = 0; mt < 2; mt++) {
            int r0 = wm*32 + mt*16 + g;
            ah[mt][0] = sAh[kb+t4  ][r0];   ah[mt][1] = sAh[kb+t4  ][r0+8];
            ah[mt][2] = sAh[kb+t4+4][r0];   ah[mt][3] = sAh[kb+t4+4][r0+8];
            al[mt][0] = sAl[kb+t4  ][r0];   al[mt][1] = sAl[kb+t4  ][r0+8];
            al[mt][2] = sAl[kb+t4+4][r0];   al[mt][3] = sAl[kb+t4+4][r0+8];
        }
#pragma unroll
        for (int nt = 0; nt < NT; nt++) {
            int c = wn*8*NT + nt*8 + g;
            bh[nt][0] = sBh[kb+t4][c];  bh[nt][1] = sBh[kb+t4+4][c];
            bl[nt][0] = sBl[kb+t4][c];  bl[nt][1] = sBl[kb+t4+4][c];
        }
#pragma unroll
        for (int mt = 0; mt < 2; mt++)
#pragma unroll
            for (int nt = 0; nt < NT; nt++) {
                mma_tf32(d[mt][nt], ah[mt], bh[nt]);   // hi*hi
                mma_tf32(d[mt][nt], ah[mt], bl[nt]);   // hi*lo
                mma_tf32(d[mt][nt], al[mt], bh[nt]);   // lo*hi
            }
    }
}

// ---------------- unified GEMM core ----------------
// APRE: A from pre-split hi/lo arrays (else f32, split on load). A is 64 rows, k-contig.
// BMODE: 0 = TT 64-row f32 | 1 = TT 64-row pre-split | 2 = TT 32-row f32 | 3 = TN 32-col pre-split
template<int NT, bool APRE, int BMODE>
__device__ __forceinline__ void gemm_core(
    const float* __restrict__ Af, const float* __restrict__ Ahp, const float* __restrict__ Alp,
    int lda, int m0,
    const float* __restrict__ Bf, const float* __restrict__ Bhp, const float* __restrict__ Blp,
    int ldb, int n0,
    int K, float d[2][NT][4],
    float (*sAh)[PITCH], float (*sAl)[PITCH], float (*sBh)[PITCH], float (*sBl)[PITCH])
{
    const int tid = threadIdx.x, lane = tid & 31, warp = tid >> 5;
    const int wm = warp >> 2, wn = warp & 3, g = lane >> 2, t4 = lane & 3;

    // A fetch mapping: row = tid>>2 (0..63), k = (tid&3) + 4j  -> conflict-free STS
    const int arow = tid >> 2, ak = tid & 3;
    const float* pAf = nullptr; const float* pAh = nullptr; const float* pAl = nullptr;
    if constexpr (APRE) {
        pAh = Ahp + (size_t)(m0 + arow) * lda + ak;
        pAl = Alp + (size_t)(m0 + arow) * lda + ak;
    } else {
        pAf = Af + (size_t)(m0 + arow) * lda + ak;
    }

    // B fetch mapping
    int brow = 0, bk = 0, bn2 = 0;
    const float* pBf = nullptr; const float* pBh = nullptr; const float* pBl = nullptr;
    if constexpr (BMODE == 0) {
        brow = tid >> 2; bk = tid & 3;
        pBf = Bf + (size_t)(n0 + brow) * ldb + bk;
    } else if constexpr (BMODE == 1) {
        brow = tid >> 2; bk = tid & 3;
        pBh = Bhp + (size_t)(n0 + brow) * ldb + bk;
        pBl = Blp + (size_t)(n0 + brow) * ldb + bk;
    } else if constexpr (BMODE == 2) {
        brow = tid >> 3; bk = tid & 7;
        pBf = Bf + (size_t)(n0 + brow) * ldb + bk;
    } else {
        bk = tid >> 4; bn2 = (tid & 15) * 2;
        pBh = Bhp + (size_t)bk * ldb + n0 + bn2;
        pBl = Blp + (size_t)bk * ldb + n0 + bn2;
    }

    float fa[4], fa2[4], fb[4], fb2[4];

    auto FETCH_A = [&](int k0) {
        if constexpr (APRE) {
#pragma unroll
            for (int j = 0; j < 4; j++) { fa[j] = pAh[k0 + 4*j]; fa2[j] = pAl[k0 + 4*j]; }
        } else {
#pragma unroll
            for (int j = 0; j < 4; j++) fa[j] = pAf[k0 + 4*j];
        }
    };
    auto FETCH_B = [&](int k0) {
        if constexpr (BMODE == 0) {
#pragma unroll
            for (int j = 0; j < 4; j++) fb[j] = pBf[k0 + 4*j];
        } else if constexpr (BMODE == 1) {
#pragma unroll
            for (int j = 0; j < 4; j++) { fb[j] = pBh[k0 + 4*j]; fb2[j] = pBl[k0 + 4*j]; }
        } else if constexpr (BMODE == 2) {
#pragma unroll
            for (int j = 0; j < 2; j++) fb[j] = pBf[k0 + 8*j];
        } else {
            fb[0]  = pBh[(size_t)k0 * ldb];  fb[1]  = pBh[(size_t)k0 * ldb + 1];
            fb2[0] = pBl[(size_t)k0 * ldb];  fb2[1] = pBl[(size_t)k0 * ldb + 1];
        }
    };
    auto STORE_A = [&](int buf) {
        if constexpr (APRE) {
#pragma unroll
            for (int j = 0; j < 4; j++) {
                sAh[buf*16 + ak + 4*j][arow] = fa[j];
                sAl[buf*16 + ak + 4*j][arow] = fa2[j];
            }
        } else {
#pragma unroll
            for (int j = 0; j < 4; j++) {
                float2 s = splitf(fa[j]);
                sAh[buf*16 + ak + 4*j][arow] = s.x;
                sAl[buf*16 + ak + 4*j][arow] = s.y;
            }
        }
    };
    auto STORE_B = [&](int buf) {
        if constexpr (BMODE == 0) {
#pragma unroll
            for (int j = 0; j < 4; j++) {
                float2 s = splitf(fb[j]);
                sBh[buf*16 + bk + 4*j][brow] = s.x;
                sBl[buf*16 + bk + 4*j][brow] = s.y;
            }
        } else if constexpr (BMODE == 1) {
#pragma unroll
            for (int j = 0; j < 4; j++) {
                sBh[buf*16 + bk + 4*j][brow] = fb[j];
                sBl[buf*16 + bk + 4*j][brow] = fb2[j];
            }
        } else if constexpr (BMODE == 2) {
#pragma unroll
            for (int j = 0; j < 2; j++) {
                float2 s = splitf(fb[j]);
                sBh[buf*16 + bk + 8*j][brow] = s.x;
                sBl[buf*16 + bk + 8*j][brow] = s.y;
            }
        } else {
            sBh[buf*16 + bk][bn2]   = fb[0];
            sBh[buf*16 + bk][bn2+1] = fb[1];
            sBl[buf*16 + bk][bn2]   = fb2[0];
            sBl[buf*16 + bk][bn2+1] = fb2[1];
        }
    };

    FETCH_A(0); FETCH_B(0);
    STORE_A(0); STORE_B(0);
    __syncthreads();
    int buf = 0;
    for (int k0 = 16; k0 <= K; k0 += 16) {
        bool more = (k0 < K);
        if (more) { FETCH_A(k0); FETCH_B(k0); }
        stage_compute<NT>(sAh + buf*16, sAl + buf*16, sBh + buf*16, sBl + buf*16,
                          d, wm, wn, g, t4);
        if (more) {
            STORE_A(buf ^ 1); STORE_B(buf ^ 1);
            __syncthreads();
            buf ^= 1;
        }
    }
}

// ---------------------------------------------------------------------------
// Exact simulation of jax.lax.associative_scan bracketing on 1024-bit masks.
// ---------------------------------------------------------------------------
__global__ void scan_mask_kernel(const int* __restrict__ start, const int* __restrict__ done) {
    const int n[11]   = {1025,512,256,128,64,32,16,8,4,2,1};
    const int off[11] = {0,1025,1537,1793,1921,1985,2017,2033,2041,2045,2047};
    int tid = threadIdx.x;

    if (tid < 1024) { g_ksum[tid] = 0.f; g_qsum[tid] = 0.f; }

    for (int idx = tid; idx < 1025*32; idx += blockDim.x) {
        int i = idx >> 5, w = idx & 31;
        unsigned m = 0;
        if (i > 0 && ((i-1) >> 5) == w) m = 1u << ((i-1) & 31);
        g_Dm[idx] = m;
        if (w == 0) g_Dg[i] = (start[i] ? 1 : 0) | (done[i] ? 2 : 0);
    }
    __syncthreads();

    for (int d = 0; d < 10; d++) {
        int nn = n[d+1];
        int src = off[d], dst = off[d+1];
        for (int idx = tid; idx < nn*32; idx += blockDim.x) {
            int i = idx >> 5, w = idx & 31;
            int gb = g_Dg[src + 2*i + 1];
            unsigned m = 0;
            if (gb & 1) m |= g_Dm[(src + 2*i    )*32 + w];
            if (gb & 2) m |= g_Dm[(src + 2*i + 1)*32 + w];
            g_Dm[(dst + i)*32 + w] = m;
            if (w == 0) g_Dg[dst + i] = gb;
        }
        __syncthreads();
    }

    for (int w = tid; w < 32; w += blockDim.x)
        g_Sm[off[10]*32 + w] = g_Dm[off[10]*32 + w];
    __syncthreads();

    for (int d = 9; d >= 0; d--) {
        int nd = n[d];
        int src = off[d], o = off[d+1];
        for (int idx = tid; idx < nd*32; idx += blockDim.x) {
            int pos = idx >> 5, w = idx & 31;
            unsigned m;
            if (pos == 0) {
                m = g_Dm[src*32 + w];
            } else if (pos & 1) {
                m = g_Sm[(o + (pos >> 1))*32 + w];
            } else {
                int i = (pos >> 1) - 1;
                int gb = g_Dg[src + pos];
                m = 0;
                if (gb & 1) m |= g_Sm[(o + i)*32 + w];
                if (gb & 2) m |= g_Dm[(src + pos)*32 + w];
            }
            g_Sm[(src + pos)*32 + w] = m;
        }
        __syncthreads();
    }

    for (int idx = tid; idx < 1024*32; idx += blockDim.x) {
        int t = idx >> 5, w = idx & 31;
        g_M[idx] = g_Sm[(t + 1)*32 + w];
    }
}

// ---------------------------------------------------------------------------
// Projections (tensor core): k/q (elu, split + rowsums), v (split), skip (f32)
// ---------------------------------------------------------------------------
__global__ void __launch_bounds__(256) proj_kernel(
    const float* __restrict__ X,
    const float* __restrict__ Wk, const float* __restrict__ Wq,
    const float* __restrict__ Wv, const float* __restrict__ Ws,
    const float* __restrict__ bskip)
{
    __shared__ float sAh[32][PITCH], sAl[32][PITCH], sBh[32][PITCH], sBl[32][PITCH];
    __shared__ float red[64][17];
    int bx = blockIdx.x, by = blockIdx.y;
    int wsel = bx >> 2, n0 = (bx & 3) * 64, m0 = by * 64;
    const float* W = (wsel == 0) ? Wk : (wsel == 1) ? Wq : (wsel == 2) ? Wv : Ws;

    float d[2][2][4] = {};
    gemm_core<2, false, 0>(X, nullptr, nullptr, DD, m0,
                           W, nullptr, nullptr, DD, n0,
                           DD, d, sAh, sAl, sBh, sBl);

    int tid = threadIdx.x, lane = tid & 31, warp = tid >> 5;
    int wm = warp >> 2, wn = warp & 3, g = lane >> 2, t4 = lane & 3;

    float rs[2][2] = {{0.f,0.f},{0.f,0.f}};
#pragma unroll
    for (int mt = 0; mt < 2; mt++)
#pragma unroll
    for (int nt = 0; nt < 2; nt++)
#pragma unroll
    for (int h = 0; h < 2; h++)
#pragma unroll
    for (int cj = 0; cj < 2; cj++) {
        int r = m0 + wm*32 + mt*16 + g + h*8;
        int c = n0 + wn*16 + nt*8 + t4*2 + cj;
        float v = d[mt][nt][h*2 + cj];
        if (wsel < 2) {
            v = (v > 0.f) ? v : expm1f(v);
            float2 s = splitf(v);
            g_Ph[(size_t)r * LDP + wsel*256 + c] = s.x;
            g_Pl[(size_t)r * LDP + wsel*256 + c] = s.y;
            rs[mt][h] += v;
        } else if (wsel == 2) {
            float2 s = splitf(v);
            g_Ph[(size_t)r * LDP + 512 + c] = s.x;
            g_Pl[(size_t)r * LDP + 512 + c] = s.y;
        } else {
            g_P[(size_t)r * LDP + 768 + c] = v + bskip[c];
        }
    }
    if (wsel < 2) {
#pragma unroll
        for (int mt = 0; mt < 2; mt++)
#pragma unroll
        for (int h = 0; h < 2; h++)
            red[wm*32 + mt*16 + g + h*8][wn*4 + t4] = rs[mt][h];
        __syncthreads();
        if (tid < 64) {
            float s = 0.f;
#pragma unroll
            for (int x = 0; x < 16; x++) s += red[tid][x];
            atomicAdd((wsel == 0) ? &g_ksum[m0 + tid] : &g_qsum[m0 + tid], s);
        }
    }
}

// ---------------------------------------------------------------------------
// denom[t] = qsum[t] * sum_j mask(t,j)*ksum[j]
// ---------------------------------------------------------------------------
__global__ void denom_kernel() {
    __shared__ float ks[1024];
    int tid = threadIdx.x;
    for (int i = tid; i < 1024; i += 256) ks[i] = g_ksum[i];
    __syncthreads();
    int row  = blockIdx.x * 8 + (tid >> 5);
    int lane = tid & 31;
    unsigned bits = g_M[row * 32 + lane];
    float s = 0.f;
    while (bits) {
        int b = __ffs(bits) - 1;
        bits &= bits - 1;
        s += ks[lane * 32 + b];
    }
#pragma unroll
    for (int o = 16; o > 0; o >>= 1) s += __shfl_xor_sync(0xffffffffu, s, o);
    if (lane == 0) g_den[row] = s * g_qsum[row];
}

// ---------------------------------------------------------------------------
// Masked scores (tensor core), lower-triangular linearized grid (136 blocks)
// ---------------------------------------------------------------------------
__global__ void __launch_bounds__(256) scores_kernel() {
    int l = blockIdx.x;
    int bt = (int)((sqrtf(8.f * l + 1.f) - 1.f) * 0.5f);
    while ((bt + 1) * (bt + 2) / 2 <= l) bt++;
    while (bt * (bt + 1) / 2 > l) bt--;
    int bi = l - bt * (bt + 1) / 2;

    __shared__ float sAh[32][PITCH], sAl[32][PITCH], sBh[32][PITCH], sBl[32][PITCH];
    float d[2][2][4] = {};
    gemm_core<2, true, 1>(nullptr, g_Ph + 256, g_Pl + 256, LDP, bt * 64,
                          nullptr, g_Ph,       g_Pl,       LDP, bi * 64,
                          DD, d, sAh, sAl, sBh, sBl);

    int tid = threadIdx.x, lane = tid & 31, warp = tid >> 5;
    int wm = warp >> 2, wn = warp & 3, g = lane >> 2, t4 = lane & 3;
#pragma unroll
    for (int mt = 0; mt < 2; mt++)
#pragma unroll
    for (int nt = 0; nt < 2; nt++)
#pragma unroll
    for (int h = 0; h < 2; h++)
#pragma unroll
    for (int cj = 0; cj < 2; cj++) {
        int r  = bt*64 + wm*32 + mt*16 + g + h*8;
        int ki = bi*64 + wn*16 + nt*8 + t4*2 + cj;
        unsigned bit = (g_M[r * 32 + (ki >> 5)] >> (ki & 31)) & 1u;
        float v = bit ? d[mt][nt][h*2 + cj] : 0.f;
        float2 s = splitf(v);
        g_Ah[(size_t)r * TT + ki] = s.x;
        g_Al[(size_t)r * TT + ki] = s.y;
    }
}

// ---------------------------------------------------------------------------
// numer = A @ V (K truncated at diagonal), divide by clipped denom. BN=32.
// ---------------------------------------------------------------------------
__global__ void __launch_bounds__(256) numer_kernel() {
    int bn = blockIdx.x, bt = blockIdx.y;
    __shared__ float sAh[32][PITCH], sAl[32][PITCH], sBh[32][PITCH], sBl[32][PITCH];
    float d[2][1][4] = {};
    int K = (bt + 1) * 64;
    gemm_core<1, true, 3>(nullptr, g_Ah, g_Al, TT, bt * 64,
                          nullptr, g_Ph + 512, g_Pl + 512, LDP, bn * 32,
                          K, d, sAh, sAl, sBh, sBl);

    int tid = threadIdx.x, lane = tid & 31, warp = tid >> 5;
    int wm = warp >> 2, wn = warp & 3, g = lane >> 2, t4 = lane & 3;
#pragma unroll
    for (int mt = 0; mt < 2; mt++)
#pragma unroll
    for (int h = 0; h < 2; h++) {
        int r = bt*64 + wm*32 + mt*16 + g + h*8;
        float inv = 1.f / fmaxf(g_den[r], 1e-5f);
#pragma unroll
        for (int cj = 0; cj < 2; cj++) {
            int c = bn*32 + wn*8 + t4*2 + cj;
            float v = d[mt][0][h*2 + cj] * inv;
            float2 s = splitf(v);
            g_Oh[(size_t)r * HH + c] = s.x;
            g_Ol[(size_t)r * HH + c] = s.y;
        }
    }
}

// ---------------------------------------------------------------------------
// MLP GEMMs (tensor core), BN=32 -> 128 blocks each.
// ---------------------------------------------------------------------------
__device__ __forceinline__ float mishf(float v) {
    float sp = (v > 20.f) ? v : log1pf(expf(v));
    return v * tanhf(sp);
}

template <int MODE>
__global__ void __launch_bounds__(256) mlp_kernel(const float* __restrict__ W,
                                                  const float* __restrict__ bias) {
    int bn = blockIdx.x, bm = blockIdx.y;
    __shared__ float sAh[32][PITCH], sAl[32][PITCH], sBh[32][PITCH], sBl[32][PITCH];
    const float* Ahp = (MODE == 0) ? g_Oh : (MODE == 1) ? g_H1h : g_H2h;
    const float* Alp = (MODE == 0) ? g_Ol : (MODE == 1) ? g_H1l : g_H2l;
    float d[2][1][4] = {};
    gemm_core<1, true, 2>(nullptr, Ahp, Alp, HH, bm * 64,
                          W, nullptr, nullptr, HH, bn * 32,
                          HH, d, sAh, sAl, sBh, sBl);

    int tid = threadIdx.x, lane = tid & 31, warp = tid >> 5;
    int wm = warp >> 2, wn = warp & 3, g = lane >> 2, t4 = lane & 3;
#pragma unroll
    for (int mt = 0; mt < 2; mt++)
#pragma unroll
    for (int h = 0; h < 2; h++) {
        int r = bm*64 + wm*32 + mt*16 + g + h*8;
#pragma unroll
        for (int cj = 0; cj < 2; cj++) {
            int c = bn*32 + wn*8 + t4*2 + cj;
            float v = d[mt][0][h*2 + cj] + bias[c];
            if (MODE < 2) {
                v = mishf(v);
                float2 s = splitf(v);
                if (MODE == 0) { g_H1h[(size_t)r*HH + c] = s.x; g_H1l[(size_t)r*HH + c] = s.y; }
                else           { g_H2h[(size_t)r*HH + c] = s.x; g_H2l[(size_t)r*HH + c] = s.y; }
            } else {
                g_H3[(size_t)r*HH + c] = v + g_P[(size_t)r*LDP + 768 + c];
            }
        }
    }
}

// ---------------------------------------------------------------------------
// Per-row LayerNorm
// ---------------------------------------------------------------------------
__global__ void ln_kernel(const float* __restrict__ w, const float* __restrict__ b,
                          float* __restrict__ out) {
    int row = blockIdx.x, tid = threadIdx.x;
    float v = g_H3[(size_t)row * HH + tid];
    __shared__ float sh[8];
    float s = v;
#pragma unroll
    for (int o = 16; o > 0; o >>= 1) s += __shfl_xor_sync(0xffffffffu, s, o);
    if ((tid & 31) == 0) sh[tid >> 5] = s;
    __syncthreads();
    float tot = 0.f;
#pragma unroll
    for (int i = 0; i < 8; i++) tot += sh[i];
    float mean = tot * (1.f / 256.f);
    float dd = v - mean;
    float s2 = dd * dd;
#pragma unroll
    for (int o = 16; o > 0; o >>= 1) s2 += __shfl_xor_sync(0xffffffffu, s2, o);
    __syncthreads();
    if ((tid & 31) == 0) sh[tid >> 5] = s2;
    __syncthreads();
    float tot2 = 0.f;
#pragma unroll
    for (int i = 0; i < 8; i++) tot2 += sh[i];
    float var = tot2 * (1.f / 256.f);
    out[(size_t)row * HH + tid] = dd * rsqrtf(var + 1e-5f) * w[tid] + b[tid];
}

// ---------------------------------------------------------------------------
extern "C" void kernel_launch(void* const* d_in, const int* in_sizes, int n_in,
                              void* d_out, int out_size) {
    const float* x     = (const float*)d_in[0];
    const int*   start = (const int*)d_in[3];
    const int*   done  = (const int*)d_in[4];
    const float* Wk = (const float*)d_in[5];
    const float* Wq = (const float*)d_in[6];
    const float* Wv = (const float*)d_in[7];
    const float* Ws = (const float*)d_in[8];
    const float* bskip = (const float*)d_in[9];
    const float* W1 = (const float*)d_in[10];
    const float* b1 = (const float*)d_in[11];
    const float* W2 = (const float*)d_in[12];
    const float* b2 = (const float*)d_in[13];
    const float* W3 = (const float*)d_in[14];
    const float* b3 = (const float*)d_in[15];
    const float* lnw = (const float*)d_in[16];
    const float* lnb = (const float*)d_in[17];
    float* out = (float*)d_out;

    scan_mask_kernel<<<1, 1024>>>(start, done);
    proj_kernel<<<dim3(16, 16), 256>>>(x, Wk, Wq, Wv, Ws, bskip);
    denom_kernel<<<128, 256>>>();
    scores_kernel<<<136, 256>>>();
    numer_kernel<<<dim3(8, 16), 256>>>();
    mlp_kernel<0><<<dim3(8, 16), 256>>>(W1, b1);
    mlp_kernel<1><<<dim3(8, 16), 256>>>(W2, b2);
    mlp_kernel<2><<<dim3(8, 16), 256>>>(W3, b3);
    ln_kernel<<<1024, 256>>>(lnw, lnb, out);
}